// round 16
// baseline (speedup 1.0000x reference)
#include <cuda_runtime.h>
#include <cuda_bf16.h>
#include <cstdint>

// ============================================================================
// out = chain of 20 Linear(64,64) over x[524288,64], fp32.
// Affine chain => compose into ONE map (Mc, c): out = x @ Mc^T + c.
//   Compose: ONE launch, ONE 1024-thread CTA = 4 groups of 256.
//     Phase A: group g computes Cg = product of layers [5g, 5g+5)
//              (4 sequential composes, next-layer cp.async prefetch).
//     Phase B: D0 = C1 o C0 (grp0) || D1 = C3 o C2 (grp1); final = D1 o D0.
//   Apply: persistent, 4 CTAs/SM, cp.async double-buffered 64-row tiles,
//          B fragments in packed smem table (LDS.128), coalesced epilogue.
// Base sm_103 target (no tcgen05 in this build pipeline).
// ============================================================================

#define N_TOK   524288
#define DIM     64
#define TILE_R  64
#define NT      (N_TOK / TILE_R)     // 8192 tiles
#define GRID_APPLY 608               // 4 x 152 SMs
#define PIT     72                   // apply smem pitch (floats)
#define PITC    68                   // compose smem pitch (floats)
#define CHUNK   5                    // layers per compose group

struct AffineMap {
    float M[DIM * DIM];
    float c[DIM];
};
__device__ AffineMap g_final;

// ---------------------------------------------------------------------------
// helpers
// ---------------------------------------------------------------------------
__device__ __forceinline__ void split2(float2 v, uint32_t& hi, uint32_t& lo) {
    __nv_bfloat16 hx = __float2bfloat16_rn(v.x);
    __nv_bfloat16 hy = __float2bfloat16_rn(v.y);
    __nv_bfloat16 lx = __float2bfloat16_rn(v.x - __bfloat162float(hx));
    __nv_bfloat16 ly = __float2bfloat16_rn(v.y - __bfloat162float(hy));
    hi = (uint32_t)__bfloat16_as_ushort(hx) |
         ((uint32_t)__bfloat16_as_ushort(hy) << 16);
    lo = (uint32_t)__bfloat16_as_ushort(lx) |
         ((uint32_t)__bfloat16_as_ushort(ly) << 16);
}

__device__ __forceinline__ void mma16816(float* c, const uint32_t* a,
                                         uint32_t b0, uint32_t b1) {
    asm volatile(
        "mma.sync.aligned.m16n8k16.row.col.f32.bf16.bf16.f32 "
        "{%0,%1,%2,%3}, {%4,%5,%6,%7}, {%8,%9}, {%0,%1,%2,%3};\n"
        : "+f"(c[0]), "+f"(c[1]), "+f"(c[2]), "+f"(c[3])
        : "r"(a[0]), "r"(a[1]), "r"(a[2]), "r"(a[3]), "r"(b0), "r"(b1));
}

__device__ __forceinline__ uint32_t smem_u32(const void* p) {
    uint32_t a;
    asm("{ .reg .u64 t; cvta.to.shared.u64 t, %1; cvt.u32.u64 %0, t; }"
        : "=r"(a) : "l"(p));
    return a;
}

#define CP_ASYNC16(saddr, gptr) \
    asm volatile("cp.async.cg.shared.global [%0], [%1], 16;" \
                 :: "r"(saddr), "l"(gptr))
#define CP_COMMIT() asm volatile("cp.async.commit_group;")
#define CP_WAIT(n)  asm volatile("cp.async.wait_group %0;" :: "n"(n))

// ---------------------------------------------------------------------------
// compose building blocks (gt = thread id within a 256-thread group)
// ---------------------------------------------------------------------------
typedef float SmMat[PITC];

// stage one 64x64 fp32 matrix gmem -> smem (pitch PITC), 256 threads
__device__ __forceinline__ void stage_mat(uint32_t sdst,
                                          const float* __restrict__ src,
                                          int gt) {
#pragma unroll
    for (int i = 0; i < 4; i++) {
        int id = gt + i * 256;                // 0..1023
        int row = id >> 4, ch = id & 15;
        CP_ASYNC16(sdst + (uint32_t)(row * PITC + ch * 4) * 4, src + id * 4);
    }
}

// 64x64x64 product into acc regs: D = Bm @ A  (A = applied-first map).
// B-frags gathered per-kt inside the loop (keeps register count low for the
// 1024-thread compose CTA). bf16x3 (hh + hl + lh). Conflict-free @ PITC=68.
__device__ void compose_mat(const SmMat* A, const SmMat* Bm,
                            float acc[4][4], int gt) {
    const int lane = gt & 31;
    const int w    = gt >> 5;
    const int g    = lane >> 2;
    const int tig  = lane & 3;
    const int warp_r = (w >> 1) * 16;
    const int warp_c = (w & 1) * 32;

#pragma unroll
    for (int nt = 0; nt < 4; nt++)
        acc[nt][0] = acc[nt][1] = acc[nt][2] = acc[nt][3] = 0.f;

#pragma unroll
    for (int kt = 0; kt < 4; kt++) {
        int t0 = kt * 16 + 2 * tig;

        uint32_t bhi[4][2], blo[4][2];
#pragma unroll
        for (int nt = 0; nt < 4; nt++) {
            int n = warp_c + nt * 8 + g;
            float2 p0 = make_float2(A[t0 + 0][n], A[t0 + 1][n]);
            float2 p1 = make_float2(A[t0 + 8][n], A[t0 + 9][n]);
            split2(p0, bhi[nt][0], blo[nt][0]);
            split2(p1, bhi[nt][1], blo[nt][1]);
        }

        const float* ar  = &Bm[warp_r + g][0];
        const float* ar8 = &Bm[warp_r + g + 8][0];
        float2 a00 = make_float2(ar[t0], ar[t0 + 1]);
        float2 a01 = make_float2(ar[t0 + 8], ar[t0 + 9]);
        float2 a10 = make_float2(ar8[t0], ar8[t0 + 1]);
        float2 a11 = make_float2(ar8[t0 + 8], ar8[t0 + 9]);
        uint32_t ahi[4], alo[4];
        split2(a00, ahi[0], alo[0]);
        split2(a10, ahi[1], alo[1]);
        split2(a01, ahi[2], alo[2]);
        split2(a11, ahi[3], alo[3]);
#pragma unroll
        for (int nt = 0; nt < 4; nt++) {
            mma16816(acc[nt], ahi, bhi[nt][0], bhi[nt][1]);
            mma16816(acc[nt], ahi, blo[nt][0], blo[nt][1]);
            mma16816(acc[nt], alo, bhi[nt][0], bhi[nt][1]);
        }
    }
}

__device__ __forceinline__ void store_acc_smem(SmMat* D, const float acc[4][4],
                                               int gt) {
    const int lane = gt & 31;
    const int w    = gt >> 5;
    const int g    = lane >> 2;
    const int tig  = lane & 3;
    const int warp_r = (w >> 1) * 16;
    const int warp_c = (w & 1) * 32;
#pragma unroll
    for (int nt = 0; nt < 4; nt++) {
        int col = warp_c + nt * 8 + 2 * tig;
        int row = warp_r + g;
        *reinterpret_cast<float2*>(&D[row][col]) =
            make_float2(acc[nt][0], acc[nt][1]);
        *reinterpret_cast<float2*>(&D[row + 8][col]) =
            make_float2(acc[nt][2], acc[nt][3]);
    }
}

__device__ __forceinline__ void store_acc_gmem(float* D, const float acc[4][4],
                                               int gt) {
    const int lane = gt & 31;
    const int w    = gt >> 5;
    const int g    = lane >> 2;
    const int tig  = lane & 3;
    const int warp_r = (w >> 1) * 16;
    const int warp_c = (w & 1) * 32;
#pragma unroll
    for (int nt = 0; nt < 4; nt++) {
        int col = warp_c + nt * 8 + 2 * tig;
        int row = warp_r + g;
        *reinterpret_cast<float2*>(D + (size_t)row * DIM + col) =
            make_float2(acc[nt][0], acc[nt][1]);
        *reinterpret_cast<float2*>(D + (size_t)(row + 8) * DIM + col) =
            make_float2(acc[nt][2], acc[nt][3]);
    }
}

// bias: cb + dot(Bm[j][:], va[:]) for j<64 (fp32 exact)
__device__ __forceinline__ float bias_step(const SmMat* Bm, const float* va,
                                           float cbj, int j) {
    float p0 = 0.f, p1 = 0.f;
#pragma unroll
    for (int t = 0; t < DIM; t += 4) {
        float2 w0 = *reinterpret_cast<const float2*>(&Bm[j][t]);
        float2 w1 = *reinterpret_cast<const float2*>(&Bm[j][t + 2]);
        p0 += w0.x * va[t] + w0.y * va[t + 1];
        p1 += w1.x * va[t + 2] + w1.y * va[t + 3];
    }
    return cbj + (p0 + p1);
}

// compose smem: 12 matrices (3 per group) + 4 chunk biases + 2 D biases
#define CSMEM_BYTES (12 * DIM * PITC * 4 + 6 * DIM * 4)

// ---------------------------------------------------------------------------
// Single-launch composition. 1 CTA x 1024 threads = 4 groups x 256.
// Group g: Cg = L(5g+4) o ... o L(5g)   (phase A, all groups parallel)
// Phase B: D0 = C1 o C0 (grp0) || D1 = C3 o C2 (grp1); final = D1 o D0 (grp0)
// All barriers are CTA-wide and control-flow-uniform across groups.
// ---------------------------------------------------------------------------
__global__ void __launch_bounds__(1024, 1)
compose_all_kernel(const float* __restrict__ W, const float* __restrict__ bb) {
    extern __shared__ float csm[];
    SmMat* mats = reinterpret_cast<SmMat*>(csm);      // 12 * DIM rows
    float* vb = csm + 12 * DIM * PITC;                // [4][64] chunk biases
    float* vd = vb + 4 * DIM;                         // [2][64] D biases

    const int tid = threadIdx.x;
    const int grp = tid >> 8;        // 0..3
    const int gt  = tid & 255;       // 0..255

    // group-local matrix slots
    SmMat* C  = mats + (3 * grp + 0) * DIM;   // cur (chunk accumulator)
    SmMat* S0 = mats + (3 * grp + 1) * DIM;   // operand / prefetch buffers
    SmMat* S1 = mats + (3 * grp + 2) * DIM;
    float* vu = vb + grp * DIM;

    const float* Wg = W + (size_t)(CHUNK * grp) * DIM * DIM;
    float acc[4][4];

    // ---- Phase A: chunk product ----
    stage_mat(smem_u32(&C[0][0]),  Wg, gt);                       // L(5g)
    stage_mat(smem_u32(&S0[0][0]), Wg + DIM * DIM, gt);           // L(5g+1)
    CP_COMMIT();
    if (gt < DIM) vu[gt] = bb[(CHUNK * grp) * DIM + gt];
    CP_WAIT(0);
    __syncthreads();

    SmMat* op = S0;
    SmMat* nx = S1;
#pragma unroll 1
    for (int j = 1; j < CHUNK; j++) {
        // prefetch next layer while composing this one
        if (j + 1 < CHUNK) {
            stage_mat(smem_u32(&nx[0][0]),
                      Wg + (size_t)(j + 1) * DIM * DIM, gt);
            CP_COMMIT();
        }
        compose_mat(C, op, acc, gt);          // new = op @ cur
        float br = 0.f;
        if (gt < DIM)
            br = bias_step(op, vu, bb[(CHUNK * grp + j) * DIM + gt], gt);
        __syncthreads();                      // reads of C complete
        store_acc_smem(C, acc, gt);
        if (gt < DIM) vu[gt] = br;
        if (j + 1 < CHUNK) CP_WAIT(0);        // next operand landed
        __syncthreads();                      // C stored, operand visible
        SmMat* tswap = op; op = nx; nx = tswap;
    }
    // Cg now in C slot of group g; bias in vb[g]

    // ---- Phase B step 1: D0 = C1 o C0 (grp0), D1 = C3 o C2 (grp1) ----
    // store D0 -> mats slot 1 (grp0's S0), D1 -> slot 4 (grp1's S0)
    float br = 0.f;
    if (grp == 0) {
        compose_mat(mats + 0 * DIM, mats + 3 * DIM, acc, gt);   // A=C0, Bm=C1
        if (gt < DIM) br = bias_step(mats + 3 * DIM, vb, vb[DIM + gt], gt);
    } else if (grp == 1) {
        compose_mat(mats + 6 * DIM, mats + 9 * DIM, acc, gt);   // A=C2, Bm=C3
        if (gt < DIM)
            br = bias_step(mats + 9 * DIM, vb + 2 * DIM, vb[3 * DIM + gt], gt);
    }
    __syncthreads();
    if (grp == 0) {
        store_acc_smem(mats + 1 * DIM, acc, gt);
        if (gt < DIM) vd[gt] = br;
    } else if (grp == 1) {
        store_acc_smem(mats + 4 * DIM, acc, gt);
        if (gt < DIM) vd[DIM + gt] = br;
    }
    __syncthreads();

    // ---- Phase B step 2: final = D1 o D0 (grp0) ----
    if (grp == 0) {
        compose_mat(mats + 1 * DIM, mats + 4 * DIM, acc, gt);   // A=D0, Bm=D1
        store_acc_gmem(g_final.M, acc, gt);
        if (gt < DIM)
            g_final.c[gt] = bias_step(mats + 4 * DIM, vd, vd[DIM + gt], gt);
    }
}

// ---------------------------------------------------------------------------
// Apply: out = x @ Mc^T + c. Persistent, 4 CTAs/SM.
// smem: 2x[64][PIT] x-buffers (reused as output stage) + packed B-fragment
// table frag[wc2][kt4][nt4][lane32] (uint4 = {bhi0,bhi1,blo0,blo1}).
// Dynamic smem = 36864 + 16384 = 53248 B (4x = 212,992 <= 228 KB).
// ---------------------------------------------------------------------------
__global__ void __launch_bounds__(256, 4)
apply_kernel(const float* __restrict__ x, float* __restrict__ out) {
    extern __shared__ float sm[];
    float* xs0 = sm;                          // [64][PIT]
    float* xs1 = sm + TILE_R * PIT;           // [64][PIT]
    uint4* sfrag = reinterpret_cast<uint4*>(sm + 2 * TILE_R * PIT);  // 1024

    const int tid  = threadIdx.x;
    const int lane = tid & 31;
    const int w    = tid >> 5;
    const int g    = lane >> 2;
    const int tig  = lane & 3;
    const int warp_r = (w >> 1) * 16;         // 0,16,32,48
    const int warp_c = (w & 1) * 32;          // 0,32

    const uint32_t xsa0 = smem_u32(xs0);
    const uint32_t xsa1 = smem_u32(xs1);

    // prologue: prefetch first tile
    int t = blockIdx.x;
    if (t < NT) {
        const float* src = x + (size_t)t * TILE_R * DIM;
#pragma unroll
        for (int i = 0; i < 4; i++) {
            int id = tid + i * 256;           // 0..1023
            int row = id >> 4, ch = id & 15;
            CP_ASYNC16(xsa0 + (uint32_t)(row * PIT + ch * 4) * 4, src + id * 4);
        }
        CP_COMMIT();
    }

    // build B-fragment table (warps 0,1) while tile 0 flies
    if (w < 2) {
        const float* Mc = g_final.M;
#pragma unroll
        for (int kt = 0; kt < 4; kt++)
#pragma unroll
            for (int nt = 0; nt < 4; nt++) {
                int n = w * 32 + nt * 8 + g;
                const float* br = Mc + n * DIM + kt * 16 + 2 * tig;
                float2 p0 = *reinterpret_cast<const float2*>(br);
                float2 p1 = *reinterpret_cast<const float2*>(br + 8);
                uint32_t h0, l0, h1, l1;
                split2(p0, h0, l0);
                split2(p1, h1, l1);
                sfrag[((w * 4 + kt) * 4 + nt) * 32 + lane] =
                    make_uint4(h0, h1, l0, l1);
            }
    }

    // bias in regs
    float2 bias[4];
#pragma unroll
    for (int nt = 0; nt < 4; nt++) {
        int col = warp_c + nt * 8 + 2 * tig;
        bias[nt] = *reinterpret_cast<const float2*>(g_final.c + col);
    }
    __syncthreads();   // frag table visible

    const uint4* myfrag = sfrag + ((w & 1) * 4) * 4 * 32 + lane;

    int buf = 0;
    while (t < NT) {
        const int tn = t + GRID_APPLY;
        if (tn < NT) {
            const uint32_t sb = buf ? xsa0 : xsa1;
            const float* src = x + (size_t)tn * TILE_R * DIM;
#pragma unroll
            for (int i = 0; i < 4; i++) {
                int id = tid + i * 256;
                int row = id >> 4, ch = id & 15;
                CP_ASYNC16(sb + (uint32_t)(row * PIT + ch * 4) * 4, src + id * 4);
            }
            CP_COMMIT();
            CP_WAIT(1);
        } else {
            CP_WAIT(0);
        }
        __syncthreads();   // current tile resident

        float* xb = buf ? xs1 : xs0;
        const float* xr  = xb + (size_t)(warp_r + g) * PIT;
        const float* xr8 = xr + 8 * PIT;

        float acc[4][4];
#pragma unroll
        for (int nt = 0; nt < 4; nt++) {
            acc[nt][0] = bias[nt].x; acc[nt][1] = bias[nt].y;
            acc[nt][2] = bias[nt].x; acc[nt][3] = bias[nt].y;
        }

#pragma unroll
        for (int kt = 0; kt < 4; kt++) {
            int kk = kt * 16 + 2 * tig;
            float2 a00 = *reinterpret_cast<const float2*>(xr + kk);
            float2 a10 = *reinterpret_cast<const float2*>(xr8 + kk);
            float2 a01 = *reinterpret_cast<const float2*>(xr + kk + 8);
            float2 a11 = *reinterpret_cast<const float2*>(xr8 + kk + 8);
            uint32_t ahi[4], alo[4];
            split2(a00, ahi[0], alo[0]);
            split2(a10, ahi[1], alo[1]);
            split2(a01, ahi[2], alo[2]);
            split2(a11, ahi[3], alo[3]);
#pragma unroll
            for (int nt = 0; nt < 4; nt++) {
                uint4 f = myfrag[(kt * 4 + nt) * 32];
                mma16816(acc[nt], ahi, f.x, f.y);
                mma16816(acc[nt], ahi, f.z, f.w);
                mma16816(acc[nt], alo, f.x, f.y);
            }
        }

        // stage into the just-consumed buffer, then one coalesced STG pass
        float* o0 = xb + (size_t)(warp_r + g) * PIT;
        float* o8 = o0 + 8 * PIT;
#pragma unroll
        for (int nt = 0; nt < 4; nt++) {
            int col = warp_c + nt * 8 + 2 * tig;
            *reinterpret_cast<float2*>(o0 + col) =
                make_float2(acc[nt][0], acc[nt][1]);
            *reinterpret_cast<float2*>(o8 + col) =
                make_float2(acc[nt][2], acc[nt][3]);
        }
        __syncthreads();   // staged tile complete

        float* gdst = out + (size_t)t * TILE_R * DIM;
#pragma unroll
        for (int i = 0; i < 4; i++) {
            int id = tid + i * 256;          // 0..1023
            int row = id >> 4, ch = id & 15;
            float4 v = *reinterpret_cast<const float4*>(xb + row * PIT + ch * 4);
            *reinterpret_cast<float4*>(gdst + id * 4) = v;
        }
        __syncthreads();   // STG reads done before next prefetch reuses xb

        buf ^= 1;
        t = tn;
    }
}

// ---------------------------------------------------------------------------
// Launch
// ---------------------------------------------------------------------------
extern "C" void kernel_launch(void* const* d_in, const int* in_sizes, int n_in,
                              void* d_out, int out_size) {
    const float* x = (const float*)d_in[0];  // [524288, 64]
    const float* W = (const float*)d_in[1];  // [20, 64, 64]
    const float* b = (const float*)d_in[2];  // [20, 64]
    float* out = (float*)d_out;              // [524288, 64]

    const int smem_apply = (2 * TILE_R * PIT) * (int)sizeof(float) + 16384;
    cudaFuncSetAttribute(apply_kernel,
                         cudaFuncAttributeMaxDynamicSharedMemorySize,
                         smem_apply);
    cudaFuncSetAttribute(compose_all_kernel,
                         cudaFuncAttributeMaxDynamicSharedMemorySize,
                         CSMEM_BYTES);

    compose_all_kernel<<<1, 1024, CSMEM_BYTES>>>(W, b);
    apply_kernel<<<GRID_APPLY, 256, smem_apply>>>(x, out);
}